// round 1
// baseline (speedup 1.0000x reference)
#include <cuda_runtime.h>
#include <cuda_bf16.h>

// RangeLoss: mean((preds - adjusted_target)^2) over N=8M rows, F=4 cols.
// Pure HBM-streaming reduction. Row-major [N,4] float32 -> one float4 per row.

#define MAX_BLOCKS 4096
__device__ double g_partials[MAX_BLOCKS];

__global__ void rangeloss_partial_kernel(const float4* __restrict__ preds,
                                         const float4* __restrict__ target,
                                         long long n_rows) {
    const long long stride = (long long)gridDim.x * blockDim.x;
    long long idx = (long long)blockIdx.x * blockDim.x + threadIdx.x;

    double acc = 0.0;
    for (; idx < n_rows; idx += stride) {
        float4 p = preds[idx];
        float4 t = target[idx];

        // Step A, column 0
        if (fabsf(p.x) < 0.01f && t.x == 0.0f) t.x = p.x;
        if (p.x > 0.99f && p.x < 1.01f && t.x == 1.0f) t.x = p.x;
        // Step A, column 1
        if (fabsf(p.y) < 0.01f && t.y == 0.0f) t.y = p.y;
        if (p.y > 0.99f && p.y < 1.01f && t.y == 1.0f) t.y = p.y;
        // Step B, column 1 (uses post-step-A t.y)
        bool cond_hi  = p.z > 0.9f;
        bool cond_rng = (p.y * 1.05f > t.y) && (p.y * 0.95f < t.y);
        if (cond_hi || cond_rng) t.y = p.y;

        float d0 = p.x - t.x;
        float d1 = p.y - t.y;
        float d2 = p.z - t.z;
        float d3 = p.w - t.w;
        acc += (double)(d0 * d0 + d1 * d1 + d2 * d2 + d3 * d3);
    }

    // Block reduce (doubles) via shared memory
    __shared__ double sdata[256];
    int tid = threadIdx.x;
    sdata[tid] = acc;
    __syncthreads();
    for (int s = 128; s > 0; s >>= 1) {
        if (tid < s) sdata[tid] += sdata[tid + s];
        __syncthreads();
    }
    if (tid == 0) g_partials[blockIdx.x] = sdata[0];
}

__global__ void rangeloss_final_kernel(float* __restrict__ out,
                                       int n_partials,
                                       double inv_count) {
    __shared__ double sdata[1024];
    int tid = threadIdx.x;
    double acc = 0.0;
    for (int i = tid; i < n_partials; i += blockDim.x) acc += g_partials[i];
    sdata[tid] = acc;
    __syncthreads();
    for (int s = 512; s > 0; s >>= 1) {
        if (tid < s) sdata[tid] += sdata[tid + s];
        __syncthreads();
    }
    if (tid == 0) out[0] = (float)(sdata[0] * inv_count);
}

extern "C" void kernel_launch(void* const* d_in, const int* in_sizes, int n_in,
                              void* d_out, int out_size) {
    const float4* preds  = (const float4*)d_in[0];
    const float4* target = (const float4*)d_in[1];
    float* out = (float*)d_out;

    long long n_elems = (long long)in_sizes[0];   // N * 4
    long long n_rows  = n_elems / 4;

    const int threads = 256;
    int blocks = 148 * 16;  // 2368 blocks, well under MAX_BLOCKS
    if ((long long)blocks * threads > n_rows)
        blocks = (int)((n_rows + threads - 1) / threads);
    if (blocks < 1) blocks = 1;

    rangeloss_partial_kernel<<<blocks, threads>>>(preds, target, n_rows);
    rangeloss_final_kernel<<<1, 1024>>>(out, blocks, 1.0 / (double)n_elems);
}

// round 2
// speedup vs baseline: 1.1966x; 1.1966x over previous
#include <cuda_runtime.h>
#include <cuda_bf16.h>

// RangeLoss: mean((preds - adjusted_target)^2), N=8M rows, F=4 -> one float4/row.
// Single-kernel HBM-streaming reduction. Deterministic via int64 fixed-point atomics.

__device__ unsigned long long g_acc   = 0ULL;
__device__ unsigned int       g_count = 0u;

#define FXP_SCALE 268435456.0  // 2^28

__device__ __forceinline__ float row_loss(float4 p, float4 t) {
    // Step A, column 0
    if (fabsf(p.x) < 0.01f && t.x == 0.0f) t.x = p.x;
    if (p.x > 0.99f && p.x < 1.01f && t.x == 1.0f) t.x = p.x;
    // Step A, column 1
    if (fabsf(p.y) < 0.01f && t.y == 0.0f) t.y = p.y;
    if (p.y > 0.99f && p.y < 1.01f && t.y == 1.0f) t.y = p.y;
    // Step B, column 1 (uses post-step-A t.y)
    bool cond = (p.z > 0.9f) || ((p.y * 1.05f > t.y) && (p.y * 0.95f < t.y));
    if (cond) t.y = p.y;

    float d0 = p.x - t.x;
    float d1 = p.y - t.y;
    float d2 = p.z - t.z;
    float d3 = p.w - t.w;
    return d0 * d0 + d1 * d1 + d2 * d2 + d3 * d3;
}

__global__ void rangeloss_kernel(const float4* __restrict__ preds,
                                 const float4* __restrict__ target,
                                 long long n_rows,
                                 float* __restrict__ out,
                                 unsigned int n_blocks,
                                 double inv_count) {
    const long long stride  = (long long)gridDim.x * blockDim.x;
    const long long stride4 = stride * 4;
    long long base = (long long)blockIdx.x * blockDim.x + threadIdx.x;

    float facc = 0.0f;

    // Unrolled-by-4 main loop: 8 outstanding LDG.128 per iteration.
    long long idx = base;
    for (; idx + 3 * stride < n_rows; idx += stride4) {
        float4 p0 = __ldcs(&preds[idx]);
        float4 p1 = __ldcs(&preds[idx + stride]);
        float4 p2 = __ldcs(&preds[idx + 2 * stride]);
        float4 p3 = __ldcs(&preds[idx + 3 * stride]);
        float4 t0 = __ldcs(&target[idx]);
        float4 t1 = __ldcs(&target[idx + stride]);
        float4 t2 = __ldcs(&target[idx + 2 * stride]);
        float4 t3 = __ldcs(&target[idx + 3 * stride]);
        facc += row_loss(p0, t0);
        facc += row_loss(p1, t1);
        facc += row_loss(p2, t2);
        facc += row_loss(p3, t3);
    }
    // Tail
    for (; idx < n_rows; idx += stride) {
        float4 p = __ldcs(&preds[idx]);
        float4 t = __ldcs(&target[idx]);
        facc += row_loss(p, t);
    }

    // Warp reduce in double
    double acc = (double)facc;
    #pragma unroll
    for (int off = 16; off > 0; off >>= 1)
        acc += __shfl_down_sync(0xFFFFFFFFu, acc, off);

    // Cross-warp reduce via shared
    __shared__ double swarp[8];  // 256 threads = 8 warps
    int lane = threadIdx.x & 31;
    int wid  = threadIdx.x >> 5;
    if (lane == 0) swarp[wid] = acc;
    __syncthreads();

    if (threadIdx.x == 0) {
        double bsum = swarp[0];
        #pragma unroll
        for (int w = 1; w < 8; w++) bsum += swarp[w];

        // Deterministic device-wide accumulation: fixed-point int64
        unsigned long long fx = (unsigned long long)(bsum * FXP_SCALE + 0.5);
        atomicAdd(&g_acc, fx);
        __threadfence();
        unsigned int done = atomicAdd(&g_count, 1u);
        if (done == n_blocks - 1u) {
            unsigned long long total_fx = atomicAdd(&g_acc, 0ULL);
            double total = (double)total_fx / FXP_SCALE;
            out[0] = (float)(total * inv_count);
            // Reset for next graph replay
            atomicExch(&g_acc, 0ULL);
            atomicExch(&g_count, 0u);
        }
    }
}

extern "C" void kernel_launch(void* const* d_in, const int* in_sizes, int n_in,
                              void* d_out, int out_size) {
    const float4* preds  = (const float4*)d_in[0];
    const float4* target = (const float4*)d_in[1];
    float* out = (float*)d_out;

    long long n_elems = (long long)in_sizes[0];   // N * 4
    long long n_rows  = n_elems / 4;

    const int threads = 256;
    int blocks = 148 * 8;  // 2048 threads/SM: one full-occupancy resident wave
    if ((long long)blocks * threads > n_rows)
        blocks = (int)((n_rows + threads - 1) / threads);
    if (blocks < 1) blocks = 1;

    rangeloss_kernel<<<blocks, threads>>>(preds, target, n_rows, out,
                                          (unsigned int)blocks,
                                          1.0 / (double)n_elems);
}

// round 3
// speedup vs baseline: 1.2890x; 1.0772x over previous
#include <cuda_runtime.h>
#include <cuda_bf16.h>

// RangeLoss: mean((preds - adjusted_target)^2), N=8M rows, F=4 -> one float4/row.
// Single-kernel HBM-streaming reduction. Deterministic via int64 fixed-point atomics.
// R3: 32-reg budget (full occupancy), unroll-2, int32 indexing, float-only lane accum.

__device__ unsigned long long g_acc   = 0ULL;
__device__ unsigned int       g_count = 0u;

#define FXP_SCALE 268435456.0  // 2^28

__device__ __forceinline__ float row_loss(float4 p, float4 t) {
    // Step A, column 0
    if (fabsf(p.x) < 0.01f && t.x == 0.0f) t.x = p.x;
    if (p.x > 0.99f && p.x < 1.01f && t.x == 1.0f) t.x = p.x;
    // Step A, column 1
    if (fabsf(p.y) < 0.01f && t.y == 0.0f) t.y = p.y;
    if (p.y > 0.99f && p.y < 1.01f && t.y == 1.0f) t.y = p.y;
    // Step B, column 1 (uses post-step-A t.y)
    bool cond = (p.z > 0.9f) || ((p.y * 1.05f > t.y) && (p.y * 0.95f < t.y));
    if (cond) t.y = p.y;

    float d0 = p.x - t.x;
    float d1 = p.y - t.y;
    float d2 = p.z - t.z;
    float d3 = p.w - t.w;
    return d0 * d0 + d1 * d1 + d2 * d2 + d3 * d3;
}

__global__ void __launch_bounds__(256, 8)
rangeloss_kernel(const float4* __restrict__ preds,
                 const float4* __restrict__ target,
                 int n_rows,
                 float* __restrict__ out,
                 unsigned int n_blocks,
                 double inv_count) {
    const int stride  = gridDim.x * blockDim.x;
    const int stride2 = stride * 2;
    int idx = blockIdx.x * blockDim.x + threadIdx.x;

    float facc = 0.0f;

    // Unroll-by-2: 4 outstanding LDG.128, 16 data regs.
    for (; idx + stride < n_rows; idx += stride2) {
        float4 p0 = __ldcs(&preds[idx]);
        float4 t0 = __ldcs(&target[idx]);
        float4 p1 = __ldcs(&preds[idx + stride]);
        float4 t1 = __ldcs(&target[idx + stride]);
        facc += row_loss(p0, t0);
        facc += row_loss(p1, t1);
    }
    if (idx < n_rows) {
        float4 p = __ldcs(&preds[idx]);
        float4 t = __ldcs(&target[idx]);
        facc += row_loss(p, t);
    }

    // Warp reduce in float (per-lane sums are small; fp32 ample for 1e-3 tol)
    #pragma unroll
    for (int off = 16; off > 0; off >>= 1)
        facc += __shfl_down_sync(0xFFFFFFFFu, facc, off);

    __shared__ float swarp[8];  // 256 threads = 8 warps
    int lane = threadIdx.x & 31;
    int wid  = threadIdx.x >> 5;
    if (lane == 0) swarp[wid] = facc;
    __syncthreads();

    if (threadIdx.x == 0) {
        double bsum = 0.0;
        #pragma unroll
        for (int w = 0; w < 8; w++) bsum += (double)swarp[w];

        // Deterministic device-wide accumulation: fixed-point int64
        unsigned long long fx = (unsigned long long)(bsum * FXP_SCALE + 0.5);
        atomicAdd(&g_acc, fx);
        __threadfence();
        unsigned int done = atomicAdd(&g_count, 1u);
        if (done == n_blocks - 1u) {
            unsigned long long total_fx = atomicAdd(&g_acc, 0ULL);
            double total = (double)total_fx / FXP_SCALE;
            out[0] = (float)(total * inv_count);
            // Reset for next graph replay
            atomicExch(&g_acc, 0ULL);
            atomicExch(&g_count, 0u);
        }
    }
}

extern "C" void kernel_launch(void* const* d_in, const int* in_sizes, int n_in,
                              void* d_out, int out_size) {
    const float4* preds  = (const float4*)d_in[0];
    const float4* target = (const float4*)d_in[1];
    float* out = (float*)d_out;

    long long n_elems = (long long)in_sizes[0];   // N * 4
    int n_rows = (int)(n_elems / 4);

    const int threads = 256;
    int blocks = 148 * 16;  // 2368 blocks: ~2 resident generations for balance
    if ((long long)blocks * threads > (long long)n_rows)
        blocks = (n_rows + threads - 1) / threads;
    if (blocks < 1) blocks = 1;

    rangeloss_kernel<<<blocks, threads>>>(preds, target, n_rows, out,
                                          (unsigned int)blocks,
                                          1.0 / (double)n_elems);
}

// round 4
// speedup vs baseline: 1.2899x; 1.0007x over previous
#include <cuda_runtime.h>
#include <cuda_bf16.h>

// RangeLoss: mean((preds - adjusted_target)^2), N=8M rows, F=4 -> one float4/row.
// Single-kernel HBM-streaming reduction. Deterministic via int64 fixed-point atomics.
// R4: single resident wave (1184 blocks), unroll-3 (6 in-flight LDG.128), 32-reg cap.

__device__ unsigned long long g_acc   = 0ULL;
__device__ unsigned int       g_count = 0u;

#define FXP_SCALE 268435456.0  // 2^28

__device__ __forceinline__ float row_loss(float4 p, float4 t) {
    // Step A, column 0
    if (fabsf(p.x) < 0.01f && t.x == 0.0f) t.x = p.x;
    if (p.x > 0.99f && p.x < 1.01f && t.x == 1.0f) t.x = p.x;
    // Step A, column 1
    if (fabsf(p.y) < 0.01f && t.y == 0.0f) t.y = p.y;
    if (p.y > 0.99f && p.y < 1.01f && t.y == 1.0f) t.y = p.y;
    // Step B, column 1 (uses post-step-A t.y)
    bool cond = (p.z > 0.9f) || ((p.y * 1.05f > t.y) && (p.y * 0.95f < t.y));
    if (cond) t.y = p.y;

    float d0 = p.x - t.x;
    float d1 = p.y - t.y;
    float d2 = p.z - t.z;
    float d3 = p.w - t.w;
    return d0 * d0 + d1 * d1 + d2 * d2 + d3 * d3;
}

__global__ void __launch_bounds__(256, 8)
rangeloss_kernel(const float4* __restrict__ preds,
                 const float4* __restrict__ target,
                 int n_rows,
                 float* __restrict__ out,
                 unsigned int n_blocks,
                 double inv_count) {
    const int stride  = gridDim.x * blockDim.x;   // uniform -> UR offsets in SASS
    const int stride3 = stride * 3;
    int idx = blockIdx.x * blockDim.x + threadIdx.x;

    float facc = 0.0f;

    // Unroll-by-3: 6 outstanding LDG.128 per thread, addresses as ptr + UR-offset.
    for (; idx + 2 * stride < n_rows; idx += stride3) {
        const float4* pp = preds + idx;
        const float4* tp = target + idx;
        float4 p0 = __ldcs(pp);
        float4 p1 = __ldcs(pp + stride);
        float4 p2 = __ldcs(pp + 2 * stride);
        float4 t0 = __ldcs(tp);
        float4 t1 = __ldcs(tp + stride);
        float4 t2 = __ldcs(tp + 2 * stride);
        facc += row_loss(p0, t0);
        facc += row_loss(p1, t1);
        facc += row_loss(p2, t2);
    }
    for (; idx < n_rows; idx += stride) {
        float4 p = __ldcs(&preds[idx]);
        float4 t = __ldcs(&target[idx]);
        facc += row_loss(p, t);
    }

    // Warp reduce in float (per-lane sums are small; fp32 ample for 1e-3 tol)
    #pragma unroll
    for (int off = 16; off > 0; off >>= 1)
        facc += __shfl_down_sync(0xFFFFFFFFu, facc, off);

    __shared__ float swarp[8];  // 256 threads = 8 warps
    int lane = threadIdx.x & 31;
    int wid  = threadIdx.x >> 5;
    if (lane == 0) swarp[wid] = facc;
    __syncthreads();

    if (threadIdx.x == 0) {
        double bsum = 0.0;
        #pragma unroll
        for (int w = 0; w < 8; w++) bsum += (double)swarp[w];

        // Deterministic device-wide accumulation: fixed-point int64
        unsigned long long fx = (unsigned long long)(bsum * FXP_SCALE + 0.5);
        atomicAdd(&g_acc, fx);
        __threadfence();
        unsigned int done = atomicAdd(&g_count, 1u);
        if (done == n_blocks - 1u) {
            unsigned long long total_fx = atomicAdd(&g_acc, 0ULL);
            double total = (double)total_fx / FXP_SCALE;
            out[0] = (float)(total * inv_count);
            // Reset for next graph replay
            atomicExch(&g_acc, 0ULL);
            atomicExch(&g_count, 0u);
        }
    }
}

extern "C" void kernel_launch(void* const* d_in, const int* in_sizes, int n_in,
                              void* d_out, int out_size) {
    const float4* preds  = (const float4*)d_in[0];
    const float4* target = (const float4*)d_in[1];
    float* out = (float*)d_out;

    long long n_elems = (long long)in_sizes[0];   // N * 4
    int n_rows = (int)(n_elems / 4);

    const int threads = 256;
    int blocks = 148 * 8;  // exactly one resident wave at occ=8
    if ((long long)blocks * threads > (long long)n_rows)
        blocks = (n_rows + threads - 1) / threads;
    if (blocks < 1) blocks = 1;

    rangeloss_kernel<<<blocks, threads>>>(preds, target, n_rows, out,
                                          (unsigned int)blocks,
                                          1.0 / (double)n_elems);
}